// round 17
// baseline (speedup 1.0000x reference)
#include <cuda_runtime.h>
#include <math.h>

#define BB 64
#define TT 512
#define II 64
#define HH 512
#define OO 64
#define TGTN 96
#define NCTA 128
#define NTHR 512

typedef unsigned long long ull;

// ---- SMEM layout (floats) ----
#define OFF_WHH0 0            // 512*16 = 8192
#define OFF_WIH1 8192
#define OFF_WHH1 16384
#define OFF_WX   24576        // 64*16 = 1024
#define OFF_ST0  25600        // stage buf: 8192 (128k x 64b chunk)
#define OFF_ST1  33792
#define OFF_G    41984        // 512 u64 = 1024 floats
#define OFF_GX   43008        // 1024 floats (precomputed x-part gates)
#define OFF_B0   44032
#define OFF_B1   44048
#define OFF_C0   44064        // 256
#define OFF_C1   44320        // 256
#define OFF_FC   44576        // 256
#define SMEM_FLOATS 44832
#define SMEM_BYTES (SMEM_FLOATS * 4)

// ---- device globals ----
__device__ float g_hs0[(size_t)TT * HH * BB];     // [t][j][b] k-major
__device__ float g_h0buf[2 * HH * BB];
__device__ float g_h1buf[2 * HH * BB];
__device__ float g_h1T[BB * HH];                  // [b][j] for fc
__device__ float g_y[OO * BB];                    // [o][b]
__device__ float g_xT[(size_t)TT * II * BB];      // [t][i][b]
__device__ float g_gx0[(size_t)TT * NCTA * 1024]; // [t][cta][col16][b64]
__device__ float g_wt_hh0[(size_t)NCTA * HH * 16];
__device__ float g_wt_ih1[(size_t)NCTA * HH * 16];
__device__ float g_wt_hh1[(size_t)NCTA * HH * 16];
__device__ float g_wt_ih0[(size_t)NCTA * II * 16];
__device__ unsigned g_bar_count;
__device__ unsigned g_bar_gen;

__device__ __forceinline__ void grid_barrier() {
    __syncthreads();
    if (threadIdx.x == 0) {
        __threadfence();
        volatile unsigned* vgen = &g_bar_gen;
        unsigned old = *vgen;
        unsigned arr = atomicAdd(&g_bar_count, 1u);
        if (arr == NCTA - 1) {
            g_bar_count = 0;
            __threadfence();
            atomicExch(&g_bar_gen, old + 1u);
        } else {
            while (*vgen == old) { }
        }
        __threadfence();
    }
    __syncthreads();
}

__device__ __forceinline__ void fma2(ull& d, ull a, ull b) {
    asm("fma.rn.f32x2 %0, %1, %2, %0;" : "+l"(d) : "l"(a), "l"(b));
}
__device__ __forceinline__ ull addx2(ull a, ull b) {
    ull r;
    asm("add.rn.f32x2 %0, %1, %2;" : "=l"(r) : "l"(a), "l"(b));
    return r;
}
__device__ __forceinline__ ull dup2(float w) {
    ull r;
    asm("mov.b64 %0, {%1, %1};" : "=l"(r) : "f"(w));
    return r;
}
__device__ __forceinline__ void cp16(float* sdst, const float* gsrc) {
    unsigned s = (unsigned)__cvta_generic_to_shared(sdst);
    asm volatile("cp.async.cg.shared.global [%0], [%1], 16;" :: "r"(s), "l"(gsrc));
}
__device__ __forceinline__ void cp_commit() {
    asm volatile("cp.async.commit_group;" ::: "memory");
}
__device__ __forceinline__ void cp_wait0() {
    asm volatile("cp.async.wait_group 0;" ::: "memory");
}

// ---- one k-row tile: 4 cols x 4 batch-pairs ----
__device__ __forceinline__ void tile_k(const float* hr, const float* wr, ull* acc) {
    ulonglong2 h01 = *(const ulonglong2*)hr;
    ulonglong2 h23 = *(const ulonglong2*)(hr + 4);
    float4 wv = *(const float4*)wr;
    ull w0 = dup2(wv.x), w1 = dup2(wv.y), w2 = dup2(wv.z), w3 = dup2(wv.w);
    fma2(acc[0],  h01.x, w0); fma2(acc[1],  h01.y, w0);
    fma2(acc[2],  h23.x, w0); fma2(acc[3],  h23.y, w0);
    fma2(acc[4],  h01.x, w1); fma2(acc[5],  h01.y, w1);
    fma2(acc[6],  h23.x, w1); fma2(acc[7],  h23.y, w1);
    fma2(acc[8],  h01.x, w2); fma2(acc[9],  h01.y, w2);
    fma2(acc[10], h23.x, w2); fma2(acc[11], h23.y, w2);
    fma2(acc[12], h01.x, w3); fma2(acc[13], h01.y, w3);
    fma2(acc[14], h23.x, w3); fma2(acc[15], h23.y, w3);
}

// ---- K=512 GEMM, accumulate into acc; hsrc [512][64] k-major, sW [512][16] ----
__device__ void g512(const float* __restrict__ hsrc, const float* sW, float* sm,
                     ull* acc, int warp, int cq, int bp8) {
    const int tid = threadIdx.x;
    float* st0 = sm + OFF_ST0;
    float* st1 = sm + OFF_ST1;
#pragma unroll
    for (int i = 0; i < 4; i++) {
        int f = tid + i * NTHR;            // 0..2047 float4s = 8192 floats
        cp16(st0 + f * 4, hsrc + f * 4);
    }
    cp_commit();
#pragma unroll 1
    for (int ch = 0; ch < 4; ch++) {
        cp_wait0();
        __syncthreads();
        if (ch < 3) {
            float* nb = ((ch + 1) & 1) ? st1 : st0;
            const float* ns = hsrc + (ch + 1) * 8192;
#pragma unroll
            for (int i = 0; i < 4; i++) {
                int f = tid + i * NTHR;
                cp16(nb + f * 4, ns + f * 4);
            }
            cp_commit();
        }
        const float* S  = (ch & 1) ? st1 : st0;
        const float* Wc = sW + ch * 128 * 16;
#pragma unroll
        for (int i = 0; i < 8; i++) {
            int k = warp * 8 + i;          // 16 warps x 8 rows = 128
            tile_k(S + k * 64 + bp8 * 8, Wc + k * 16 + cq * 4, acc);
        }
    }
    __syncthreads();
}

// ---- K=64 GEMM (y feedback); src [64][64] k-major ----
__device__ void g64(const float* __restrict__ src, const float* sWX, float* sm,
                    ull* acc, int warp, int cq, int bp8) {
    const int tid = threadIdx.x;
    float* st = sm + OFF_ST0;
#pragma unroll
    for (int i = 0; i < 2; i++) {
        int f = tid + i * NTHR;            // 0..1023 float4s
        cp16(st + f * 4, src + f * 4);
    }
    cp_commit();
    cp_wait0();
    __syncthreads();
#pragma unroll
    for (int i = 0; i < 4; i++) {
        int k = warp * 4 + i;              // 16 warps x 4 rows = 64
        tile_k(st + k * 64 + bp8 * 8, sWX + k * 16 + cq * 4, acc);
    }
    __syncthreads();
}

// ---- step finish: cross-warp reduce (+gx) + LSTM elementwise + write ----
__device__ void step_finish(float* sm, ull* acc, int warp, int cq, int bp8,
                            const float* sB, float* sC, int cta, int use_gx,
                            float* __restrict__ dstK, float* __restrict__ dstT) {
    const int tid = threadIdx.x;
    ull* sRed = (ull*)(sm + OFF_ST0);      // 16 planes x 512 u64 = 64KB (ST0+ST1)
#pragma unroll
    for (int c = 0; c < 4; c++)
#pragma unroll
        for (int i = 0; i < 4; i++)
            sRed[warp * 512 + (cq * 4 + c) * 32 + bp8 * 4 + i] = acc[c * 4 + i];
    __syncthreads();
    ull* sG = (ull*)(sm + OFF_G);
    {
        int u = tid;                       // 512 threads x 1 u64
        ull s = sRed[u];
#pragma unroll
        for (int w = 1; w < 16; w++) s = addx2(s, sRed[w * 512 + u]);
        if (use_gx) s = addx2(s, ((const ull*)(sm + OFF_GX))[u]);
        sG[u] = s;
    }
    __syncthreads();
    if (tid < 256) {
        const float* gf = sm + OFF_G;
        int b = tid & 63, jj = tid >> 6;
        float gi  = gf[(0  + jj) * 64 + b] + sB[0  + jj];
        float gfo = gf[(4  + jj) * 64 + b] + sB[4  + jj];
        float gg  = gf[(8  + jj) * 64 + b] + sB[8  + jj];
        float go  = gf[(12 + jj) * 64 + b] + sB[12 + jj];
        float c  = sC[tid];
        float si = 1.f / (1.f + expf(-gi));
        float sf = 1.f / (1.f + expf(-gfo));
        float so = 1.f / (1.f + expf(-go));
        float cn = sf * c + si * tanhf(gg);
        float hn = so * tanhf(cn);
        sC[tid] = cn;
        int j = cta * 4 + jj;
        dstK[j * 64 + b] = hn;
        if (dstT) dstT[(size_t)b * HH + j] = hn;
    }
    grid_barrier();
}

// ---- prep kernels ----
extern "C" __global__ void prep_w_kernel(
    const float* __restrict__ Wih0, const float* __restrict__ Whh0,
    const float* __restrict__ Wih1, const float* __restrict__ Whh1) {
    int cta = blockIdx.x, tid = threadIdx.x;
    for (int idx = tid; idx < 512 * 16; idx += blockDim.x) {
        int k = idx >> 4, ng = idx & 15;
        int n = (ng >> 2) * HH + cta * 4 + (ng & 3);
        g_wt_hh0[(size_t)cta * 8192 + idx] = Whh0[(size_t)n * HH + k];
        g_wt_ih1[(size_t)cta * 8192 + idx] = Wih1[(size_t)n * HH + k];
        g_wt_hh1[(size_t)cta * 8192 + idx] = Whh1[(size_t)n * HH + k];
    }
    for (int idx = tid; idx < 64 * 16; idx += blockDim.x) {
        int k = idx >> 4, ng = idx & 15;
        int n = (ng >> 2) * HH + cta * 4 + (ng & 3);
        g_wt_ih0[(size_t)cta * 1024 + idx] = Wih0[(size_t)n * II + k];
    }
}
extern "C" __global__ void prep_x_kernel(const float* __restrict__ x) {
    int t = blockIdx.x, tid = threadIdx.x;
    for (int idx = tid; idx < 64 * 64; idx += blockDim.x) {
        int i = idx >> 6, b = idx & 63;
        g_xT[(size_t)t * 4096 + i * 64 + b] = x[(size_t)b * TT * II + t * II + i];
    }
}
// gx0[t][cta][col][b] = sum_i Wih0T[cta][i][col] * xT[t][i][b]
extern "C" __global__ void prep_gx_kernel() {
    __shared__ float sx[4096];
    __shared__ float sw[1024];
    int t = blockIdx.x, tid = threadIdx.x;   // 256 threads
    for (int i = 0; i < 16; i++)
        sx[tid + i * 256] = g_xT[(size_t)t * 4096 + tid + i * 256];
    int col = tid >> 4, b0 = (tid & 15) * 4;
#pragma unroll 1
    for (int cta = 0; cta < NCTA; cta++) {
        __syncthreads();
        for (int i = 0; i < 4; i++)
            sw[tid + i * 256] = g_wt_ih0[(size_t)cta * 1024 + tid + i * 256];
        __syncthreads();
        float s0 = 0.f, s1 = 0.f, s2 = 0.f, s3 = 0.f;
#pragma unroll
        for (int k = 0; k < 64; k++) {
            float w = sw[k * 16 + col];
            float4 h = *(const float4*)(sx + k * 64 + b0);
            s0 += w * h.x; s1 += w * h.y; s2 += w * h.z; s3 += w * h.w;
        }
        float4 r; r.x = s0; r.y = s1; r.z = s2; r.w = s3;
        *(float4*)(&g_gx0[((size_t)t * NCTA + cta) * 1024 + col * 64 + b0]) = r;
    }
}

// ---- main persistent kernel ----
extern "C" __global__ void __launch_bounds__(NTHR, 1)
lstm_persistent_kernel(
    const float* __restrict__ bih0, const float* __restrict__ bhh0,
    const float* __restrict__ bih1, const float* __restrict__ bhh1,
    const float* __restrict__ Wfc,  const float* __restrict__ bfc,
    float* __restrict__ out)
{
    extern __shared__ float sm[];
    const int cta  = blockIdx.x;
    const int tid  = threadIdx.x;
    const int warp = tid >> 5;      // 0..15
    const int lane = tid & 31;
    const int bp8  = lane >> 2;     // 0..7 : batch octet
    const int cq   = lane & 3;      // 0..3 : col quad

    for (int idx = tid; idx < 8192; idx += NTHR) {
        sm[OFF_WHH0 + idx] = g_wt_hh0[(size_t)cta * 8192 + idx];
        sm[OFF_WIH1 + idx] = g_wt_ih1[(size_t)cta * 8192 + idx];
        sm[OFF_WHH1 + idx] = g_wt_hh1[(size_t)cta * 8192 + idx];
    }
    for (int idx = tid; idx < 1024; idx += NTHR)
        sm[OFF_WX + idx] = g_wt_ih0[(size_t)cta * 1024 + idx];
    if (tid < 16) {
        int n = (tid >> 2) * HH + cta * 4 + (tid & 3);
        sm[OFF_B0 + tid] = bih0[n] + bhh0[n];
        sm[OFF_B1 + tid] = bih1[n] + bhh1[n];
    }
    if (tid < 256) {
        sm[OFF_C0 + tid] = 0.f;
        sm[OFF_C1 + tid] = 0.f;
    }
    __syncthreads();

    ull acc[16];

    // ===== encoder layer 0 (x-part precomputed in g_gx0) =====
    for (int t = 0; t < TT; t++) {
#pragma unroll
        for (int i = 0; i < 16; i++) acc[i] = 0ull;
        const float* gxs = g_gx0 + ((size_t)t * NCTA + cta) * 1024;
        if (tid < 256) cp16(sm + OFF_GX + tid * 4, gxs + tid * 4);
        if (t > 0) {
            g512(g_hs0 + (size_t)(t - 1) * HH * BB, sm + OFF_WHH0, sm, acc,
                 warp, cq, bp8);
        } else {
            cp_commit(); cp_wait0(); __syncthreads();
        }
        step_finish(sm, acc, warp, cq, bp8, sm + OFF_B0, sm + OFF_C0, cta, 1,
                    g_hs0 + (size_t)t * HH * BB, nullptr);
    }

    // ===== encoder layer 1 =====
    for (int t = 0; t < TT; t++) {
#pragma unroll
        for (int i = 0; i < 16; i++) acc[i] = 0ull;
        g512(g_hs0 + (size_t)t * HH * BB, sm + OFF_WIH1, sm, acc, warp, cq, bp8);
        if (t > 0)
            g512(g_h1buf + (size_t)((t - 1) & 1) * HH * BB, sm + OFF_WHH1, sm, acc,
                 warp, cq, bp8);
        step_finish(sm, acc, warp, cq, bp8, sm + OFF_B1, sm + OFF_C1, cta, 0,
                    g_h1buf + (size_t)(t & 1) * HH * BB, nullptr);
    }

    // ===== decoder =====
    for (int s = 0; s < TGTN; s++) {
        // phase A : layer-0 cell
#pragma unroll
        for (int i = 0; i < 16; i++) acc[i] = 0ull;
        {
            int use_gx = 0;
            if (s == 0) {
                const float* gxs = g_gx0 + ((size_t)(TT - 1) * NCTA + cta) * 1024;
                if (tid < 256) cp16(sm + OFF_GX + tid * 4, gxs + tid * 4);
                use_gx = 1;
            } else {
                g64(g_y, sm + OFF_WX, sm, acc, warp, cq, bp8);
            }
            const float* hp = (s == 0) ? (g_hs0 + (size_t)(TT - 1) * HH * BB)
                                       : (g_h0buf + (size_t)((s - 1) & 1) * HH * BB);
            g512(hp, sm + OFF_WHH0, sm, acc, warp, cq, bp8);
            step_finish(sm, acc, warp, cq, bp8, sm + OFF_B0, sm + OFF_C0, cta,
                        use_gx, g_h0buf + (size_t)(s & 1) * HH * BB, nullptr);
        }
        // phase B : layer-1 cell
#pragma unroll
        for (int i = 0; i < 16; i++) acc[i] = 0ull;
        {
            g512(g_h0buf + (size_t)(s & 1) * HH * BB, sm + OFF_WIH1, sm, acc,
                 warp, cq, bp8);
            const float* hp = (s == 0) ? (g_h1buf + (size_t)HH * BB)
                                       : (g_h1buf + (size_t)((s - 1) & 1) * HH * BB);
            g512(hp, sm + OFF_WHH1, sm, acc, warp, cq, bp8);
            step_finish(sm, acc, warp, cq, bp8, sm + OFF_B1, sm + OFF_C1, cta, 0,
                        g_h1buf + (size_t)(s & 1) * HH * BB, g_h1T);
        }
        // phase C : y = h1 @ Wfc^T + bfc
        {
            float* sFc = sm + OFF_FC;
            if (tid < 256) {
                int p = tid >> 3, q = tid & 7;
                int flat = cta * 32 + p;
                int bb = flat >> 6, oo = flat & 63;
                const float4* h4 = (const float4*)(g_h1T + (size_t)bb * HH + q * 64);
                const float4* w4 = (const float4*)(Wfc + (size_t)oo * HH + q * 64);
                float sum = 0.f;
#pragma unroll
                for (int k = 0; k < 16; k++) {
                    float4 a = h4[k], w = w4[k];
                    sum += a.x * w.x + a.y * w.y + a.z * w.z + a.w * w.w;
                }
                sFc[p * 8 + q] = sum;
            }
            __syncthreads();
            if (tid < 32) {
                int fl = cta * 32 + tid;
                int bb2 = fl >> 6, oo2 = fl & 63;
                float tot = bfc[oo2];
#pragma unroll
                for (int j = 0; j < 8; j++) tot += sFc[tid * 8 + j];
                g_y[oo2 * 64 + bb2] = tot;
                out[(size_t)bb2 * TGTN * OO + (size_t)s * OO + oo2] = tot;
            }
            grid_barrier();
        }
    }
}

// ---- host launch ----
extern "C" void kernel_launch(void* const* d_in, const int* in_sizes, int n_in,
                              void* d_out, int out_size) {
    (void)in_sizes; (void)n_in; (void)out_size;
    const float* x    = (const float*)d_in[0];
    const float* Wih0 = (const float*)d_in[1];
    const float* Whh0 = (const float*)d_in[2];
    const float* bih0 = (const float*)d_in[3];
    const float* bhh0 = (const float*)d_in[4];
    const float* Wih1 = (const float*)d_in[5];
    const float* Whh1 = (const float*)d_in[6];
    const float* bih1 = (const float*)d_in[7];
    const float* bhh1 = (const float*)d_in[8];
    const float* Wfc  = (const float*)d_in[9];
    const float* bfc  = (const float*)d_in[10];

    prep_w_kernel<<<NCTA, 256>>>(Wih0, Whh0, Wih1, Whh1);
    prep_x_kernel<<<TT, 256>>>(x);
    prep_gx_kernel<<<TT, 256>>>();

    cudaFuncSetAttribute(lstm_persistent_kernel,
                         cudaFuncAttributeMaxDynamicSharedMemorySize, SMEM_BYTES);
    lstm_persistent_kernel<<<NCTA, NTHR, SMEM_BYTES>>>(
        bih0, bhh0, bih1, bhh1, Wfc, bfc, (float*)d_out);
}